// round 12
// baseline (speedup 1.0000x reference)
#include <cuda_runtime.h>
#include <cuda_bf16.h>
#include <stdint.h>
#include <math.h>

// Problem shape (fixed by dataset)
static constexpr int Bb = 4;
static constexpr int Ss = 2048;
static constexpr int Ee = 1024;
static constexpr int Dd = 1024;

// ---------------- scratch (proven 163 MB budget) ----------------
__device__ float g_q[(size_t)Bb * Ss * Dd];   // 32 MB
__device__ float g_k[(size_t)Bb * Ss * Dd];   // 32 MB
__device__ float g_v[(size_t)Bb * Ss * Dd];   // 32 MB
__device__ float g_p[(size_t)Bb * Ss * Ss];   // 67 MB; front 46 MB aliased as
                                              // bf16 planes during proj phase
// plane offsets (in bf16 elements) inside g_p
static constexpr size_t XN = (size_t)Bb * Ss * Ee;   // 8388608
static constexpr size_t WN = (size_t)Dd * Ee;        // 1048576
// layout: [xh | xl | wqh | wql | wkh | wkl | wvh | wvl]  (46.1 MB < 67 MB)

// ---------------- mma helpers ----------------
__device__ __forceinline__ uint32_t smem_u32(const void* p) {
    uint32_t a;
    asm("{ .reg .u64 t; cvta.to.shared.u64 t, %1; cvt.u32.u64 %0, t; }" : "=r"(a) : "l"(p));
    return a;
}
#define SW64(o) ((o) ^ (((o) >> 3) & 0x30))

__device__ __forceinline__ void ldsm4(uint32_t* r, uint32_t a) {
    asm volatile("ldmatrix.sync.aligned.m8n8.x4.shared.b16 {%0,%1,%2,%3}, [%4];"
        : "=r"(r[0]), "=r"(r[1]), "=r"(r[2]), "=r"(r[3]) : "r"(a));
}
__device__ __forceinline__ void mma_bf16(float* d, const uint32_t* a,
                                         uint32_t b0, uint32_t b1) {
    asm volatile("mma.sync.aligned.m16n8k16.row.col.f32.bf16.bf16.f32 "
        "{%0,%1,%2,%3}, {%4,%5,%6,%7}, {%8,%9}, {%0,%1,%2,%3};"
        : "+f"(d[0]), "+f"(d[1]), "+f"(d[2]), "+f"(d[3])
        : "r"(a[0]), "r"(a[1]), "r"(a[2]), "r"(a[3]), "r"(b0), "r"(b1));
}

static constexpr int SM_AH = 0;
static constexpr int SM_AL = 8192;
static constexpr int SM_BH = 16384;
static constexpr int SM_BL = 24576;
static constexpr int SM_TOTAL = 32768;

__device__ __forceinline__ void load_plane(char* smem, int off,
                                           const __nv_bfloat16* src, long ld,
                                           int tid) {
    #pragma unroll
    for (int j = 0; j < 2; j++) {
        int i = tid + j * 256;
        int row = i >> 2, c16 = i & 3;
        uint4 v = *(const uint4*)(src + (size_t)row * ld + c16 * 8);
        *(uint4*)(smem + off + SW64(row * 64 + c16 * 16)) = v;
    }
}

// fp32 -> (hi, lo) bf16 planes written into the g_p alias region
__global__ void __launch_bounds__(256) convert_split(
    const float* __restrict__ src, size_t hi_off, size_t lo_off)
{
    __nv_bfloat16* hi = ((__nv_bfloat16*)g_p) + hi_off;
    __nv_bfloat16* lo = ((__nv_bfloat16*)g_p) + lo_off;
    size_t i = (size_t)blockIdx.x * 256 + threadIdx.x;
    float4 v = ((const float4*)src)[i];
    __nv_bfloat16 h0 = __float2bfloat16(v.x), h1 = __float2bfloat16(v.y);
    __nv_bfloat16 h2 = __float2bfloat16(v.z), h3 = __float2bfloat16(v.w);
    __nv_bfloat16 l0 = __float2bfloat16(v.x - __bfloat162float(h0));
    __nv_bfloat16 l1 = __float2bfloat16(v.y - __bfloat162float(h1));
    __nv_bfloat16 l2 = __float2bfloat16(v.z - __bfloat162float(h2));
    __nv_bfloat16 l3 = __float2bfloat16(v.w - __bfloat162float(h3));
    __nv_bfloat162 hA = __halves2bfloat162(h0, h1), hB = __halves2bfloat162(h2, h3);
    __nv_bfloat162 lA = __halves2bfloat162(l0, l1), lB = __halves2bfloat162(l2, l3);
    ((uint32_t*)hi)[i * 2]     = *(uint32_t*)&hA;
    ((uint32_t*)hi)[i * 2 + 1] = *(uint32_t*)&hB;
    ((uint32_t*)lo)[i * 2]     = *(uint32_t*)&lA;
    ((uint32_t*)lo)[i * 2 + 1] = *(uint32_t*)&lB;
}

// QKV projection via split-bf16 mma (z selects W/output); fp32 output.
__global__ void __launch_bounds__(256, 2) proj_mma()
{
    __shared__ __align__(128) char smem[SM_TOTAL];
    int bx = blockIdx.x, by = blockIdx.y, bz = blockIdx.z;
    const __nv_bfloat16* base = (const __nv_bfloat16*)g_p;
    const __nv_bfloat16* Xh = base;
    const __nv_bfloat16* Xl = base + XN;
    const __nv_bfloat16* Wh = base + 2 * XN + (size_t)(2 * bz) * WN;
    const __nv_bfloat16* Wl = Wh + WN;
    float* C = (bz == 0) ? g_q : (bz == 1) ? g_k : g_v;

    const __nv_bfloat16* Ah = Xh + (size_t)(by * 128) * Ee;
    const __nv_bfloat16* Al = Xl + (size_t)(by * 128) * Ee;
    const __nv_bfloat16* Bh = Wh + (size_t)(bx * 128) * Ee;
    const __nv_bfloat16* Bl = Wl + (size_t)(bx * 128) * Ee;

    uint32_t sb = smem_u32(smem);
    int tid = threadIdx.x, lane = tid & 31, wid = tid >> 5;
    int wm = (wid & 3) * 32, wn = (wid >> 2) * 64;
    int r8 = lane & 7, sel = lane >> 3;

    int arb0 = (wm + (sel & 1) * 8 + r8) * 64 + (sel >> 1) * 16;
    int arb1 = arb0 + 16 * 64;
    int brb[4];
    #pragma unroll
    for (int j = 0; j < 4; j++)
        brb[j] = (wn + j * 16 + (sel & 1) * 8 + r8) * 64 + (sel >> 1) * 16;

    float acc[2][8][4] = {};

    for (int c = 0; c < Ee / 32; c++) {
        long co = (long)c * 32;
        load_plane(smem, SM_AH, Ah + co, Ee, tid);
        load_plane(smem, SM_AL, Al + co, Ee, tid);
        load_plane(smem, SM_BH, Bh + co, Ee, tid);
        load_plane(smem, SM_BL, Bl + co, Ee, tid);
        __syncthreads();

        #pragma unroll
        for (int ks = 0; ks < 2; ks++) {
            int kb = ks * 32;
            uint32_t ah0[4], ah1[4], al0[4], al1[4];
            ldsm4(ah0, sb + SM_AH + SW64(arb0 + kb));
            ldsm4(ah1, sb + SM_AH + SW64(arb1 + kb));
            ldsm4(al0, sb + SM_AL + SW64(arb0 + kb));
            ldsm4(al1, sb + SM_AL + SW64(arb1 + kb));
            #pragma unroll
            for (int j = 0; j < 4; j++) {
                uint32_t bh[4], bl[4];
                ldsm4(bh, sb + SM_BH + SW64(brb[j] + kb));
                ldsm4(bl, sb + SM_BL + SW64(brb[j] + kb));
                mma_bf16(acc[0][2 * j],     ah0, bh[0], bh[2]);
                mma_bf16(acc[0][2 * j + 1], ah0, bh[1], bh[3]);
                mma_bf16(acc[1][2 * j],     ah1, bh[0], bh[2]);
                mma_bf16(acc[1][2 * j + 1], ah1, bh[1], bh[3]);
                mma_bf16(acc[0][2 * j],     ah0, bl[0], bl[2]);
                mma_bf16(acc[0][2 * j + 1], ah0, bl[1], bl[3]);
                mma_bf16(acc[1][2 * j],     ah1, bl[0], bl[2]);
                mma_bf16(acc[1][2 * j + 1], ah1, bl[1], bl[3]);
                mma_bf16(acc[0][2 * j],     al0, bh[0], bh[2]);
                mma_bf16(acc[0][2 * j + 1], al0, bh[1], bh[3]);
                mma_bf16(acc[1][2 * j],     al1, bh[0], bh[2]);
                mma_bf16(acc[1][2 * j + 1], al1, bh[1], bh[3]);
            }
        }
        __syncthreads();
    }

    int rbase = by * 128 + wm + (lane >> 2);
    int cbase = bx * 128 + wn + (lane & 3) * 2;
    #pragma unroll
    for (int i = 0; i < 2; i++)
        #pragma unroll
        for (int jn = 0; jn < 8; jn++)
            #pragma unroll
            for (int h = 0; h < 2; h++) {
                int row = rbase + i * 16 + h * 8;
                int col = cbase + jn * 8;
                *(float2*)(C + (size_t)row * Dd + col) =
                    make_float2(acc[i][jn][h * 2], acc[i][jn][h * 2 + 1]);
            }
}

// =================== R5-verbatim fp32 pipeline ===================
#define BM 128
#define BN 128
#define BK 16
#define TM 8
#define TN 8

#define COMPUTE_TILE(buf)                                                     \
    _Pragma("unroll")                                                         \
    for (int kk = 0; kk < BK; kk++) {                                         \
        float4 a0 = *(const float4*)&As[buf][kk][tr];                         \
        float4 a1 = *(const float4*)&As[buf][kk][tr + 4];                     \
        float4 b0 = *(const float4*)&Bs[buf][kk][tc];                         \
        float4 b1 = *(const float4*)&Bs[buf][kk][tc + 4];                     \
        float ra[8] = {a0.x, a0.y, a0.z, a0.w, a1.x, a1.y, a1.z, a1.w};       \
        float rb[8] = {b0.x, b0.y, b0.z, b0.w, b1.x, b1.y, b1.z, b1.w};       \
        _Pragma("unroll")                                                     \
        for (int i = 0; i < TM; i++)                                          \
            _Pragma("unroll")                                                 \
            for (int j = 0; j < TN; j++)                                      \
                acc[i][j] += ra[i] * rb[j];                                   \
    }

#define STORE_KT(dst, b_, v0, v1)                                             \
    dst[b_][lc4 + 0][lrow]      = v0.x;                                       \
    dst[b_][lc4 + 1][lrow]      = v0.y;                                       \
    dst[b_][lc4 + 2][lrow]      = v0.z;                                       \
    dst[b_][lc4 + 3][lrow]      = v0.w;                                       \
    dst[b_][lc4 + 0][lrow + 64] = v1.x;                                       \
    dst[b_][lc4 + 1][lrow + 64] = v1.y;                                       \
    dst[b_][lc4 + 2][lrow + 64] = v1.z;                                       \
    dst[b_][lc4 + 3][lrow + 64] = v1.w;

#define EPILOGUE(Cp, N_)                                                      \
    _Pragma("unroll")                                                         \
    for (int i = 0; i < TM; i++) {                                            \
        float* crow = Cp + (size_t)(by * BM + tr + i) * N_ + bx * BN + tc;    \
        *(float4*)(crow)     = make_float4(acc[i][0], acc[i][1], acc[i][2], acc[i][3]); \
        *(float4*)(crow + 4) = make_float4(acc[i][4], acc[i][5], acc[i][6], acc[i][7]); \
    }

__global__ void __launch_bounds__(256, 2) scores_nt()
{
    int bx = blockIdx.x, by = blockIdx.y, bz = blockIdx.z;
    if (bx > by) return;

    const int K = Dd, N = Ss;
    const float* A = g_q + (size_t)bz * Ss * Dd;
    const float* B = g_k + (size_t)bz * Ss * Dd;
    float*       C = g_p + (size_t)bz * Ss * Ss;

    __shared__ float As[2][BK][BM];
    __shared__ float Bs[2][BK][BN];

    int tid = threadIdx.x;
    int tr = (tid >> 4) * TM, tc = (tid & 15) * TN;
    int lrow = tid >> 2, lc4 = (tid & 3) * 4;

    const float* Ab = A + (size_t)(by * BM + lrow) * K + lc4;
    const float* Bt = B + (size_t)(bx * BN + lrow) * K + lc4;

    float4 pa0 = *(const float4*)(Ab);
    float4 pa1 = *(const float4*)(Ab + (size_t)64 * K);
    float4 pb0 = *(const float4*)(Bt);
    float4 pb1 = *(const float4*)(Bt + (size_t)64 * K);
    STORE_KT(As, 0, pa0, pa1)
    STORE_KT(Bs, 0, pb0, pb1)
    __syncthreads();

    float acc[TM][TN] = {};
    int buf = 0;
    const int niter = K / BK;
    for (int it = 0; it < niter; ++it) {
        if (it + 1 < niter) {
            int k0n = (it + 1) * BK;
            pa0 = *(const float4*)(Ab + k0n);
            pa1 = *(const float4*)(Ab + (size_t)64 * K + k0n);
            pb0 = *(const float4*)(Bt + k0n);
            pb1 = *(const float4*)(Bt + (size_t)64 * K + k0n);
        }
        COMPUTE_TILE(buf)
        if (it + 1 < niter) {
            int nb = buf ^ 1;
            STORE_KT(As, nb, pa0, pa1)
            STORE_KT(Bs, nb, pb0, pb1)
            __syncthreads();
            buf = nb;
        }
    }
    EPILOGUE(C, N)
}

__global__ void __launch_bounds__(256) softmax_causal()
{
    const int S = Ss;
    int row = blockIdx.x;
    int b = row >> 11, s = row & (S - 1);
    float* p = g_p + (size_t)b * S * S + (size_t)s * S;
    int L = s + 1;
    const float scale = 0.03125f;
    int tid = threadIdx.x;

    __shared__ float red[8];

    float m = -1e30f;
    for (int i = tid; i < L; i += 256) m = fmaxf(m, p[i]);
    #pragma unroll
    for (int o = 16; o; o >>= 1) m = fmaxf(m, __shfl_xor_sync(0xFFFFFFFFu, m, o));
    if ((tid & 31) == 0) red[tid >> 5] = m;
    __syncthreads();
    if (tid == 0) {
        float mm = red[0];
        #pragma unroll
        for (int i = 1; i < 8; i++) mm = fmaxf(mm, red[i]);
        red[0] = mm;
    }
    __syncthreads();
    m = red[0] * scale;
    __syncthreads();

    float sum = 0.f;
    for (int i = tid; i < L; i += 256) sum += __expf(p[i] * scale - m);
    #pragma unroll
    for (int o = 16; o; o >>= 1) sum += __shfl_xor_sync(0xFFFFFFFFu, sum, o);
    if ((tid & 31) == 0) red[tid >> 5] = sum;
    __syncthreads();
    if (tid == 0) {
        float ss = 0.f;
        #pragma unroll
        for (int i = 0; i < 8; i++) ss += red[i];
        red[0] = ss;
    }
    __syncthreads();
    float inv = 1.0f / red[0];

    for (int i = tid; i < S; i += 256)
        p[i] = (i < L) ? __expf(p[i] * scale - m) * inv : 0.0f;
}

__global__ void __launch_bounds__(256, 2) av_nn(float* __restrict__ out)
{
    int bx = blockIdx.x, by = blockIdx.y, bz = blockIdx.z;
    const int K = Ss, N = Dd;
    const float* A  = g_p + (size_t)bz * Ss * Ss;
    const float* Bm = g_v + (size_t)bz * Ss * Dd;
    float*       C  = out + (size_t)bz * Ss * Dd;

    int kmax = (by + 1) * BM;
    if (kmax > K) kmax = K;

    __shared__ float As[2][BK][BM];
    __shared__ float Bs[2][BK][BN];

    int tid = threadIdx.x;
    int tr = (tid >> 4) * TM, tc = (tid & 15) * TN;
    int lrow = tid >> 2, lc4 = (tid & 3) * 4;
    int brow = tid >> 5, bcc = (tid & 31) * 4;

    const float* Ab = A + (size_t)(by * BM + lrow) * K + lc4;
    const float* Bbp = Bm + bx * BN + bcc;

    float4 pa0 = *(const float4*)(Ab);
    float4 pa1 = *(const float4*)(Ab + (size_t)64 * K);
    float4 pb0 = *(const float4*)(Bbp + (size_t)brow * N);
    float4 pb1 = *(const float4*)(Bbp + (size_t)(brow + 8) * N);
    STORE_KT(As, 0, pa0, pa1)
    *(float4*)&Bs[0][brow][bcc]     = pb0;
    *(float4*)&Bs[0][brow + 8][bcc] = pb1;
    __syncthreads();

    float acc[TM][TN] = {};
    int buf = 0;
    const int niter = kmax / BK;
    for (int it = 0; it < niter; ++it) {
        if (it + 1 < niter) {
            int k0n = (it + 1) * BK;
            pa0 = *(const float4*)(Ab + k0n);
            pa1 = *(const float4*)(Ab + (size_t)64 * K + k0n);
            pb0 = *(const float4*)(Bbp + (size_t)(k0n + brow) * N);
            pb1 = *(const float4*)(Bbp + (size_t)(k0n + brow + 8) * N);
        }
        COMPUTE_TILE(buf)
        if (it + 1 < niter) {
            int nb = buf ^ 1;
            STORE_KT(As, nb, pa0, pa1)
            *(float4*)&Bs[nb][brow][bcc]     = pb0;
            *(float4*)&Bs[nb][brow + 8][bcc] = pb1;
            __syncthreads();
            buf = nb;
        }
    }
    EPILOGUE(C, N)
}

// ---------------- launch ----------------
extern "C" void kernel_launch(void* const* d_in, const int* in_sizes, int n_in,
                              void* d_out, int out_size)
{
    const float* x  = (const float*)d_in[0];
    const float* wq = (const float*)d_in[1];
    const float* wk = (const float*)d_in[2];
    const float* wv = (const float*)d_in[3];
    float* out = (float*)d_out;

    dim3 blk(256);

    // bf16 planes into g_p alias region (dies before scores_nt writes g_p)
    convert_split<<<(int)(XN / 4 / 256), blk>>>(x,  0, XN);
    convert_split<<<(int)(WN / 4 / 256), blk>>>(wq, 2 * XN,          2 * XN + WN);
    convert_split<<<(int)(WN / 4 / 256), blk>>>(wk, 2 * XN + 2 * WN, 2 * XN + 3 * WN);
    convert_split<<<(int)(WN / 4 / 256), blk>>>(wv, 2 * XN + 4 * WN, 2 * XN + 5 * WN);

    // projections on tensor path (split-bf16 mma.sync)
    proj_mma<<<dim3(Dd / 128, (Bb * Ss) / 128, 3), blk>>>();

    // proven fp32 attention pipeline
    scores_nt<<<dim3(Ss / BN, Ss / BM, Bb), blk>>>();
    softmax_causal<<<Bb * Ss, blk>>>();
    av_nn<<<dim3(Dd / BN, Ss / BM, Bb), blk>>>(out);
}

// round 13
// speedup vs baseline: 1.7984x; 1.7984x over previous
#include <cuda_runtime.h>
#include <cuda_bf16.h>
#include <stdint.h>
#include <math.h>

// Problem shape (fixed by dataset)
static constexpr int Bb = 4;
static constexpr int Ss = 2048;
static constexpr int Ee = 1024;
static constexpr int Dd = 1024;

// ---------------- scratch (proven 163 MB budget — unchanged from R5) ----------
__device__ float g_q[(size_t)Bb * Ss * Dd];   // 32 MB; reused as V^T after scores
__device__ float g_k[(size_t)Bb * Ss * Dd];   // 32 MB
__device__ float g_v[(size_t)Bb * Ss * Dd];   // 32 MB
__device__ float g_p[(size_t)Bb * Ss * Ss];   // 67 MB

// ---------------- mma helpers ----------------
__device__ __forceinline__ uint32_t smem_u32(const void* p) {
    uint32_t a;
    asm("{ .reg .u64 t; cvta.to.shared.u64 t, %1; cvt.u32.u64 %0, t; }" : "=r"(a) : "l"(p));
    return a;
}
#define SW64(o) ((o) ^ (((o) >> 3) & 0x30))

__device__ __forceinline__ void ldsm4(uint32_t* r, uint32_t a) {
    asm volatile("ldmatrix.sync.aligned.m8n8.x4.shared.b16 {%0,%1,%2,%3}, [%4];"
        : "=r"(r[0]), "=r"(r[1]), "=r"(r[2]), "=r"(r[3]) : "r"(a));
}
__device__ __forceinline__ void mma_bf16(float* d, const uint32_t* a,
                                         uint32_t b0, uint32_t b1) {
    asm volatile("mma.sync.aligned.m16n8k16.row.col.f32.bf16.bf16.f32 "
        "{%0,%1,%2,%3}, {%4,%5,%6,%7}, {%8,%9}, {%0,%1,%2,%3};"
        : "+f"(d[0]), "+f"(d[1]), "+f"(d[2]), "+f"(d[3])
        : "r"(a[0]), "r"(a[1]), "r"(a[2]), "r"(a[3]), "r"(b0), "r"(b1));
}

// static smem: 4 planes of 128x32 bf16 (8 KB each) = 32 KB
static constexpr int SM_AH = 0;
static constexpr int SM_AL = 8192;
static constexpr int SM_BH = 16384;
static constexpr int SM_BL = 24576;
static constexpr int SM_TOTAL = 32768;

__device__ __forceinline__ uint32_t pack_bf2(float x, float y) {
    __nv_bfloat162 h = __halves2bfloat162(__float2bfloat16(x), __float2bfloat16(y));
    return *(uint32_t*)&h;
}
// convert 8 fp32 -> 8 hi-bf16 (uint4... actually 2 uint32) + 8 lo-bf16
__device__ __forceinline__ void cvt8(const float4 u, const float4 v,
                                     uint4& hi, uint4& lo) {
    float f[8] = {u.x, u.y, u.z, u.w, v.x, v.y, v.z, v.w};
    uint32_t hw[4], lw[4];
    #pragma unroll
    for (int p = 0; p < 4; p++) {
        __nv_bfloat16 h0 = __float2bfloat16(f[2 * p]);
        __nv_bfloat16 h1 = __float2bfloat16(f[2 * p + 1]);
        float l0 = f[2 * p]     - __bfloat162float(h0);
        float l1 = f[2 * p + 1] - __bfloat162float(h1);
        __nv_bfloat162 hh = __halves2bfloat162(h0, h1);
        __nv_bfloat162 ll = __halves2bfloat162(__float2bfloat16(l0), __float2bfloat16(l1));
        hw[p] = *(uint32_t*)&hh;
        lw[p] = *(uint32_t*)&ll;
    }
    hi = make_uint4(hw[0], hw[1], hw[2], hw[3]);
    lo = make_uint4(lw[0], lw[1], lw[2], lw[3]);
}

// Pipelined split-bf16 NT GEMM core: C(128x128 fp32 regs) = A(128xK) * B(128xK)^T
// A, B are fp32 row-major (K contiguous), converted to hi/lo bf16 on the fly.
// acc[i][jn][r]: row = wm + i*16 + lane/4 + (r>=2 ? 8:0),
//               col = wn + jn*8 + (lane%4)*2 + (r&1)
__device__ __forceinline__ void core(float (&acc)[2][8][4], char* smem,
    const float* A, long ldA, const float* B, long ldB, int nchunks)
{
    uint32_t sb = smem_u32(smem);
    int tid = threadIdx.x, lane = tid & 31, wid = tid >> 5;
    int wm = (wid & 3) * 32, wn = (wid >> 2) * 64;
    int r8 = lane & 7, sel = lane >> 3;

    int arb0 = (wm + (sel & 1) * 8 + r8) * 64 + (sel >> 1) * 16;
    int arb1 = arb0 + 16 * 64;
    int brb[4];
    #pragma unroll
    for (int j = 0; j < 4; j++)
        brb[j] = (wn + j * 16 + (sel & 1) * 8 + r8) * 64 + (sel >> 1) * 16;

    // load mapping: row = tid>>1, k-half = (tid&1)*16
    int lrow = tid >> 1, lkh = (tid & 1) * 16;
    const float* ap = A + (size_t)lrow * ldA + lkh;
    const float* bp = B + (size_t)lrow * ldB + lkh;
    int sa0 = SW64(lrow * 64 + lkh * 2);
    int sa1 = SW64(lrow * 64 + lkh * 2 + 16);

    float4 a0 = *(const float4*)(ap);
    float4 a1 = *(const float4*)(ap + 4);
    float4 a2 = *(const float4*)(ap + 8);
    float4 a3 = *(const float4*)(ap + 12);
    float4 b0 = *(const float4*)(bp);
    float4 b1 = *(const float4*)(bp + 4);
    float4 b2 = *(const float4*)(bp + 8);
    float4 b3 = *(const float4*)(bp + 12);

    for (int c = 0; c < nchunks; c++) {
        // convert + store current chunk
        uint4 hi, lo;
        cvt8(a0, a1, hi, lo);
        *(uint4*)(smem + SM_AH + sa0) = hi;
        *(uint4*)(smem + SM_AL + sa0) = lo;
        cvt8(a2, a3, hi, lo);
        *(uint4*)(smem + SM_AH + sa1) = hi;
        *(uint4*)(smem + SM_AL + sa1) = lo;
        cvt8(b0, b1, hi, lo);
        *(uint4*)(smem + SM_BH + sa0) = hi;
        *(uint4*)(smem + SM_BL + sa0) = lo;
        cvt8(b2, b3, hi, lo);
        *(uint4*)(smem + SM_BH + sa1) = hi;
        *(uint4*)(smem + SM_BL + sa1) = lo;
        __syncthreads();

        // prefetch next chunk (overlaps the compute below)
        if (c + 1 < nchunks) {
            const float* apn = ap + (size_t)(c + 1) * 32;
            const float* bpn = bp + (size_t)(c + 1) * 32;
            a0 = *(const float4*)(apn);
            a1 = *(const float4*)(apn + 4);
            a2 = *(const float4*)(apn + 8);
            a3 = *(const float4*)(apn + 12);
            b0 = *(const float4*)(bpn);
            b1 = *(const float4*)(bpn + 4);
            b2 = *(const float4*)(bpn + 8);
            b3 = *(const float4*)(bpn + 12);
        }

        #pragma unroll
        for (int ks = 0; ks < 2; ks++) {
            int kb = ks * 32;
            uint32_t ah0[4], ah1[4], al0[4], al1[4];
            ldsm4(ah0, sb + SM_AH + SW64(arb0 + kb));
            ldsm4(ah1, sb + SM_AH + SW64(arb1 + kb));
            ldsm4(al0, sb + SM_AL + SW64(arb0 + kb));
            ldsm4(al1, sb + SM_AL + SW64(arb1 + kb));
            #pragma unroll
            for (int j = 0; j < 4; j++) {
                uint32_t bh[4], bl[4];
                ldsm4(bh, sb + SM_BH + SW64(brb[j] + kb));
                ldsm4(bl, sb + SM_BL + SW64(brb[j] + kb));
                mma_bf16(acc[0][2 * j],     ah0, bh[0], bh[2]);
                mma_bf16(acc[0][2 * j + 1], ah0, bh[1], bh[3]);
                mma_bf16(acc[1][2 * j],     ah1, bh[0], bh[2]);
                mma_bf16(acc[1][2 * j + 1], ah1, bh[1], bh[3]);
                mma_bf16(acc[0][2 * j],     ah0, bl[0], bl[2]);
                mma_bf16(acc[0][2 * j + 1], ah0, bl[1], bl[3]);
                mma_bf16(acc[1][2 * j],     ah1, bl[0], bl[2]);
                mma_bf16(acc[1][2 * j + 1], ah1, bl[1], bl[3]);
                mma_bf16(acc[0][2 * j],     al0, bh[0], bh[2]);
                mma_bf16(acc[0][2 * j + 1], al0, bh[1], bh[3]);
                mma_bf16(acc[1][2 * j],     al1, bh[0], bh[2]);
                mma_bf16(acc[1][2 * j + 1], al1, bh[1], bh[3]);
            }
        }
        __syncthreads();
    }
}

// epilogue: acc -> fp32 C (row-major, ldC), tile origin (m0, n0)
__device__ __forceinline__ void epilogue(const float (&acc)[2][8][4],
                                         float* C, long ldC, int m0, int n0)
{
    int tid = threadIdx.x, lane = tid & 31, wid = tid >> 5;
    int wm = (wid & 3) * 32, wn = (wid >> 2) * 64;
    int rbase = m0 + wm + (lane >> 2);
    int cbase = n0 + wn + (lane & 3) * 2;
    #pragma unroll
    for (int i = 0; i < 2; i++)
        #pragma unroll
        for (int jn = 0; jn < 8; jn++)
            #pragma unroll
            for (int h = 0; h < 2; h++) {
                int row = rbase + i * 16 + h * 8;
                int col = cbase + jn * 8;
                *(float2*)(C + (size_t)row * ldC + col) =
                    make_float2(acc[i][jn][h * 2], acc[i][jn][h * 2 + 1]);
            }
}

// ---------------- kernels ----------------

// QKV projection: z selects W/output. C = x @ W^T (NT).
__global__ void __launch_bounds__(256, 2) proj_mma(
    const float* __restrict__ x,
    const float* __restrict__ wq, const float* __restrict__ wk,
    const float* __restrict__ wv)
{
    __shared__ __align__(128) char smem[SM_TOTAL];
    int bx = blockIdx.x, by = blockIdx.y, bz = blockIdx.z;
    const float* W = (bz == 0) ? wq : (bz == 1) ? wk : wv;
    float* C = (bz == 0) ? g_q : (bz == 1) ? g_k : g_v;

    float acc[2][8][4] = {};
    core(acc, smem, x + (size_t)(by * 128) * Ee, Ee,
         W + (size_t)(bx * 128) * Ee, Ee, Ee / 32);
    epilogue(acc, C, Dd, by * 128, bx * 128);
}

// scores = q @ k^T per batch (NT), causal tile skip.
__global__ void __launch_bounds__(256, 2) scores_mma()
{
    int bx = blockIdx.x, by = blockIdx.y, bz = blockIdx.z;
    if (bx > by) return;
    __shared__ __align__(128) char smem[SM_TOTAL];

    const float* A = g_q + (size_t)bz * Ss * Dd + (size_t)(by * 128) * Dd;
    const float* B = g_k + (size_t)bz * Ss * Dd + (size_t)(bx * 128) * Dd;
    float* C = g_p + (size_t)bz * Ss * Ss;

    float acc[2][8][4] = {};
    core(acc, smem, A, Dd, B, Dd, Dd / 32);
    epilogue(acc, C, Ss, by * 128, bx * 128);
}

// V [t,d] -> V^T [d,t] fp32 into g_q (dead after scores). grid (32, 64, 4).
__global__ void __launch_bounds__(256) transpose_v()
{
    __shared__ float t[32][33];
    int bz = blockIdx.z;
    const float* src = g_v + (size_t)bz * Ss * Dd;
    float* dst = g_q + (size_t)bz * Dd * Ss;       // [Dd][Ss]
    int d0 = blockIdx.x * 32, t0 = blockIdx.y * 32;
    int tx = threadIdx.x & 31, ty = threadIdx.x >> 5;

    #pragma unroll
    for (int p = 0; p < 4; p++)
        t[ty + p * 8][tx] = src[(size_t)(t0 + ty + p * 8) * Dd + d0 + tx];
    __syncthreads();
    #pragma unroll
    for (int p = 0; p < 4; p++)
        dst[(size_t)(d0 + ty + p * 8) * Ss + t0 + tx] = t[tx][ty + p * 8];
}

// Row-wise causal softmax on g_p (R5-verbatim).
__global__ void __launch_bounds__(256) softmax_causal()
{
    const int S = Ss;
    int row = blockIdx.x;
    int b = row >> 11, s = row & (S - 1);
    float* p = g_p + (size_t)b * S * S + (size_t)s * S;
    int L = s + 1;
    const float scale = 0.03125f;
    int tid = threadIdx.x;

    __shared__ float red[8];

    float m = -1e30f;
    for (int i = tid; i < L; i += 256) m = fmaxf(m, p[i]);
    #pragma unroll
    for (int o = 16; o; o >>= 1) m = fmaxf(m, __shfl_xor_sync(0xFFFFFFFFu, m, o));
    if ((tid & 31) == 0) red[tid >> 5] = m;
    __syncthreads();
    if (tid == 0) {
        float mm = red[0];
        #pragma unroll
        for (int i = 1; i < 8; i++) mm = fmaxf(mm, red[i]);
        red[0] = mm;
    }
    __syncthreads();
    m = red[0] * scale;
    __syncthreads();

    float sum = 0.f;
    for (int i = tid; i < L; i += 256) sum += __expf(p[i] * scale - m);
    #pragma unroll
    for (int o = 16; o; o >>= 1) sum += __shfl_xor_sync(0xFFFFFFFFu, sum, o);
    if ((tid & 31) == 0) red[tid >> 5] = sum;
    __syncthreads();
    if (tid == 0) {
        float ss = 0.f;
        #pragma unroll
        for (int i = 0; i < 8; i++) ss += red[i];
        red[0] = ss;
    }
    __syncthreads();
    float inv = 1.0f / red[0];

    for (int i = tid; i < S; i += 256)
        p[i] = (i < L) ? __expf(p[i] * scale - m) * inv : 0.0f;
}

// out = P @ V  via NT core with B = V^T (in g_q). Causal k-cutoff.
__global__ void __launch_bounds__(256, 2) av_mma(float* __restrict__ out)
{
    int bx = blockIdx.x, by = blockIdx.y, bz = blockIdx.z;
    __shared__ __align__(128) char smem[SM_TOTAL];

    const float* A = g_p + (size_t)bz * Ss * Ss + (size_t)(by * 128) * Ss;
    const float* B = g_q + (size_t)bz * Dd * Ss + (size_t)(bx * 128) * Ss; // V^T
    float* C = out + (size_t)bz * Ss * Dd;

    float acc[2][8][4] = {};
    core(acc, smem, A, Ss, B, Ss, (by + 1) * 4);   // k <= (by+1)*128
    epilogue(acc, C, Dd, by * 128, bx * 128);
}

// ---------------- launch ----------------
extern "C" void kernel_launch(void* const* d_in, const int* in_sizes, int n_in,
                              void* d_out, int out_size)
{
    const float* x  = (const float*)d_in[0];
    const float* wq = (const float*)d_in[1];
    const float* wk = (const float*)d_in[2];
    const float* wv = (const float*)d_in[3];
    float* out = (float*)d_out;

    dim3 blk(256);

    proj_mma<<<dim3(Dd / 128, (Bb * Ss) / 128, 3), blk>>>(x, wq, wk, wv);
    scores_mma<<<dim3(Ss / 128, Ss / 128, Bb), blk>>>();
    transpose_v<<<dim3(Dd / 32, Ss / 32, Bb), blk>>>();   // g_q := V^T (q dead)
    softmax_causal<<<Bb * Ss, blk>>>();
    av_mma<<<dim3(Dd / 128, Ss / 128, Bb), blk>>>(out);
}